// round 1
// baseline (speedup 1.0000x reference)
#include <cuda_runtime.h>

// BoundarySeg: out[b,j,0:768]   = sum_{d=0..5} w[b,j,d] * hidden[b, min(j+d,L-1), :]
//              out[b,j,768:1536]= hidden[b,j,:] * sum_d w[b,j,d]
// with w[b,j,d] = span_adjacency[b, j, j+d] if j+d < L else 0.
//
// Shapes fixed by the dataset: B=16, L=1024, H=768.
// in[0] = span_adjacency (B,L,L,1) fp32, in[1] = bound_hidden (B,L,H) fp32,
// out = (B,L,2H) fp32.

#define BB 16
#define LL 1024
#define HH 768
#define HV (HH / 4)   // 192 float4 per row
#define TJ 8          // j's per CTA
#define SPAN 6

__global__ __launch_bounds__(HV)
void boundary_seg_kernel(const float* __restrict__ adj,
                         const float* __restrict__ hid,
                         float* __restrict__ out)
{
    const int tile = blockIdx.x;          // b * (LL/TJ) + jt
    const int b  = tile / (LL / TJ);
    const int j0 = (tile % (LL / TJ)) * TJ;
    const int c  = threadIdx.x;           // which float4 column of H

    const float4* __restrict__ hid4 =
        reinterpret_cast<const float4*>(hid) + (size_t)b * LL * HV;
    float4* __restrict__ out4 = reinterpret_cast<float4*>(out);
    const float* __restrict__ adjb = adj + (size_t)b * LL * LL;

    // Sliding window of hidden rows j..j+5 (clamped), one float4 each.
    float4 v[SPAN];
#pragma unroll
    for (int d = 0; d < SPAN; d++) {
        int r = j0 + d; if (r > LL - 1) r = LL - 1;
        v[d] = hid4[(size_t)r * HV + c];
    }

#pragma unroll
    for (int jj = 0; jj < TJ; jj++) {
        const int j = j0 + jj;
        const float* __restrict__ arow = adjb + (size_t)j * LL;

        float w[SPAN];
        float wsum = 0.0f;
#pragma unroll
        for (int d = 0; d < SPAN; d++) {
            const int col = j + d;
            const float wd = (col < LL) ? __ldg(arow + col) : 0.0f;
            w[d] = wd;
            wsum += wd;
        }

        float4 f;
        f.x = w[0] * v[0].x; f.y = w[0] * v[0].y;
        f.z = w[0] * v[0].z; f.w = w[0] * v[0].w;
#pragma unroll
        for (int d = 1; d < SPAN; d++) {
            f.x = fmaf(w[d], v[d].x, f.x);
            f.y = fmaf(w[d], v[d].y, f.y);
            f.z = fmaf(w[d], v[d].z, f.z);
            f.w = fmaf(w[d], v[d].w, f.w);
        }

        float4 s;
        s.x = v[0].x * wsum; s.y = v[0].y * wsum;
        s.z = v[0].z * wsum; s.w = v[0].w * wsum;

        const size_t obase = ((size_t)b * LL + j) * (size_t)(2 * HV);
        out4[obase + c]      = f;
        out4[obase + HV + c] = s;

        // slide the window: v[d] <- hidden[min(j+1+d, L-1)]
#pragma unroll
        for (int d = 0; d < SPAN - 1; d++) v[d] = v[d + 1];
        int r = j + SPAN; if (r > LL - 1) r = LL - 1;
        v[SPAN - 1] = hid4[(size_t)r * HV + c];
    }
}

extern "C" void kernel_launch(void* const* d_in, const int* in_sizes, int n_in,
                              void* d_out, int out_size)
{
    const float* adj = (const float*)d_in[0];   // (B,L,L,1)
    const float* hid = (const float*)d_in[1];   // (B,L,H)
    float* out = (float*)d_out;                 // (B,L,2H)

    const int grid = BB * (LL / TJ);            // 2048 CTAs
    boundary_seg_kernel<<<grid, HV>>>(adj, hid, out);
}

// round 2
// speedup vs baseline: 1.1096x; 1.1096x over previous
#include <cuda_runtime.h>
#include <cstdint>

// BoundarySeg: out[b,j,0:768]   = sum_{d=0..5} w[b,j,d] * hidden[b, min(j+d,L-1), :]
//              out[b,j,768:1536]= hidden[b,j,:] * sum_d w[b,j,d]
// w[b,j,d] = span_adjacency[b, j, j+d] if j+d < L else 0.
// B=16, L=1024, H=768. All fp32.
//
// Strategy: CTA = 8 consecutive j's of one batch. TMA bulk-copies the 13
// contiguous hidden rows (40KB) into smem; compute threads keep a 6-row
// sliding window in registers fed by conflict-free LDS.128.

#define BB 16
#define LL 1024
#define HH 768
#define HV (HH / 4)            // 192 float4 per row
#define TJ 8                   // j's per CTA
#define SPAN 6
#define NROWS (TJ + SPAN - 1)  // 13 rows staged

__device__ __forceinline__ uint32_t smem_u32(const void* p) {
    uint32_t a;
    asm("{ .reg .u64 t; cvta.to.shared.u64 t, %1; cvt.u32.u64 %0, t; }"
        : "=r"(a) : "l"(p));
    return a;
}

__global__ __launch_bounds__(HV)
void boundary_seg_kernel(const float* __restrict__ adj,
                         const float* __restrict__ hid,
                         float* __restrict__ out)
{
    __shared__ __align__(16) float4 srows[NROWS * HV];   // 39936 B
    __shared__ float wsm[TJ][SPAN];
    __shared__ __align__(8) uint64_t mbar;

    const int tile = blockIdx.x;           // b * 128 + jt
    const int b  = tile >> 7;
    const int j0 = (tile & 127) * TJ;
    const int t  = threadIdx.x;            // float4 column of H

    const int rl = min(NROWS, LL - j0);    // rows actually available
    const uint32_t nbytes = (uint32_t)rl * HV * (uint32_t)sizeof(float4);

    const uint32_t s_rows = smem_u32(srows);
    const uint32_t s_mbar = smem_u32(&mbar);

    if (t == 0) {
        asm volatile("mbarrier.init.shared::cta.b64 [%0], %1;"
                     :: "r"(s_mbar), "r"(1) : "memory");
    }
    __syncthreads();

    if (t == 0) {
        asm volatile("mbarrier.arrive.expect_tx.shared::cta.b64 _, [%0], %1;"
                     :: "r"(s_mbar), "r"(nbytes) : "memory");
        const float* src = hid + ((size_t)b * LL + j0) * HH;
        asm volatile(
            "cp.async.bulk.shared::cluster.global.mbarrier::complete_tx::bytes "
            "[%0], [%1], %2, [%3];"
            :: "r"(s_rows), "l"(src), "r"(nbytes), "r"(s_mbar) : "memory");
    }

    // Weights: 48 scattered L2-hit loads, overlapped with the TMA.
    if (t < TJ * SPAN) {
        const int jj = t / SPAN;
        const int d  = t - jj * SPAN;
        const int col = j0 + jj + d;
        float w = 0.0f;
        if (col < LL)
            w = __ldg(adj + ((size_t)b * LL + (j0 + jj)) * LL + col);
        wsm[jj][d] = w;
    }
    __syncthreads();

    // Wait for the TMA bulk copy.
    {
        uint32_t done;
        do {
            asm volatile(
                "{ .reg .pred p;\n\t"
                "  mbarrier.try_wait.parity.shared::cta.b64 p, [%1], %2;\n\t"
                "  selp.b32 %0, 1, 0, p; }"
                : "=r"(done) : "r"(s_mbar), "r"(0u) : "memory");
        } while (!done);
    }

    const int rmax = rl - 1;

    // Sliding register window of 6 rows (this thread's float4 column).
    float4 v[SPAN];
#pragma unroll
    for (int d = 0; d < SPAN; d++)
        v[d] = srows[min(d, rmax) * HV + t];

    float4* __restrict__ out4 = reinterpret_cast<float4*>(out);

#pragma unroll
    for (int jj = 0; jj < TJ; jj++) {
        const float w0 = wsm[jj][0], w1 = wsm[jj][1], w2 = wsm[jj][2];
        const float w3 = wsm[jj][3], w4 = wsm[jj][4], w5 = wsm[jj][5];
        const float wsum = ((w0 + w1) + (w2 + w3)) + (w4 + w5);

        float4 f;
        f.x = w0 * v[0].x; f.y = w0 * v[0].y;
        f.z = w0 * v[0].z; f.w = w0 * v[0].w;
        f.x = fmaf(w1, v[1].x, f.x); f.y = fmaf(w1, v[1].y, f.y);
        f.z = fmaf(w1, v[1].z, f.z); f.w = fmaf(w1, v[1].w, f.w);
        f.x = fmaf(w2, v[2].x, f.x); f.y = fmaf(w2, v[2].y, f.y);
        f.z = fmaf(w2, v[2].z, f.z); f.w = fmaf(w2, v[2].w, f.w);
        f.x = fmaf(w3, v[3].x, f.x); f.y = fmaf(w3, v[3].y, f.y);
        f.z = fmaf(w3, v[3].z, f.z); f.w = fmaf(w3, v[3].w, f.w);
        f.x = fmaf(w4, v[4].x, f.x); f.y = fmaf(w4, v[4].y, f.y);
        f.z = fmaf(w4, v[4].z, f.z); f.w = fmaf(w4, v[4].w, f.w);
        f.x = fmaf(w5, v[5].x, f.x); f.y = fmaf(w5, v[5].y, f.y);
        f.z = fmaf(w5, v[5].z, f.z); f.w = fmaf(w5, v[5].w, f.w);

        float4 s;
        s.x = v[0].x * wsum; s.y = v[0].y * wsum;
        s.z = v[0].z * wsum; s.w = v[0].w * wsum;

        const size_t obase = ((size_t)b * LL + (j0 + jj)) * (size_t)(2 * HV);
        out4[obase + t]      = f;
        out4[obase + HV + t] = s;

        // Slide the window.
#pragma unroll
        for (int d = 0; d < SPAN - 1; d++) v[d] = v[d + 1];
        v[SPAN - 1] = srows[min(jj + SPAN, rmax) * HV + t];
    }
}

extern "C" void kernel_launch(void* const* d_in, const int* in_sizes, int n_in,
                              void* d_out, int out_size)
{
    const float* adj = (const float*)d_in[0];   // (B,L,L,1)
    const float* hid = (const float*)d_in[1];   // (B,L,H)
    float* out = (float*)d_out;                 // (B,L,2H)

    const int grid = BB * (LL / TJ);            // 2048 CTAs
    boundary_seg_kernel<<<grid, HV>>>(adj, hid, out);
}